// round 13
// baseline (speedup 1.0000x reference)
#include <cuda_runtime.h>
#include <cuda_fp16.h>
#include <math.h>
#include <stdint.h>

#define TT  2048
#define DD  1024
#define HH  512
#define HSS 1024
#define EE  8
#define BK  32
#define NST 4

// stage sizes in halves
#define GLU_STGH 8704                  // A 128x32 = 4096, B1 32x72 = 2304, B3 2304
#define GLU_SMEMB (NST * GLU_STGH * 2) // 69632 B
#define DN_STGH  8448                  // A 4096, B 32x136 = 4352
#define DN_SMEMB  (NST * DN_STGH * 2)  // 67584 B

// ---------------- scratch ----------------------------------------------------
__device__ __half g_xh  [(size_t)TT * DD];        // fp16 input
__device__ __half g_hsh [(size_t)TT * HSS];       // fp16 shared hidden
__device__ __half g_hidh[(size_t)EE * TT * HH];   // fp16 routed hidden
__device__ __half g_w1h [(size_t)EE * DD * HH];
__device__ __half g_w3h [(size_t)EE * DD * HH];
__device__ __half g_w2h [(size_t)EE * HH * DD];
__device__ __half g_ws1h[(size_t)DD * HSS];
__device__ __half g_ws3h[(size_t)DD * HSS];
__device__ __half g_ws2h[(size_t)HSS * DD];
__device__ int    g_cnt[EE];
__device__ int    g_tok[EE * TT];
__device__ float  g_wt [EE * TT];

// ---------------- helpers ----------------------------------------------------
__device__ __forceinline__ uint32_t smem_u32(const void* p) {
    uint32_t a;
    asm("{ .reg .u64 t; cvta.to.shared.u64 t, %1; cvt.u32.u64 %0, t; }" : "=r"(a) : "l"(p));
    return a;
}
#define CP16(dst, src) \
    asm volatile("cp.async.cg.shared.global [%0], [%1], 16;" :: "r"((uint32_t)(dst)), "l"(src))
#define CP_COMMIT() asm volatile("cp.async.commit_group;" ::: "memory")
#define CP_WAIT2()  asm volatile("cp.async.wait_group 2;" ::: "memory")

#define LDSM4(r0, r1, r2, r3, addr) \
    asm volatile("ldmatrix.sync.aligned.m8n8.x4.shared.b16 {%0,%1,%2,%3}, [%4];" \
        : "=r"(r0), "=r"(r1), "=r"(r2), "=r"(r3) : "r"(addr))
#define LDSM4T(r0, r1, r2, r3, addr) \
    asm volatile("ldmatrix.sync.aligned.m8n8.x4.trans.shared.b16 {%0,%1,%2,%3}, [%4];" \
        : "=r"(r0), "=r"(r1), "=r"(r2), "=r"(r3) : "r"(addr))

__device__ __forceinline__ void mmah(float* c, const uint32_t* a, uint32_t b0, uint32_t b1) {
    asm volatile(
        "mma.sync.aligned.m16n8k16.row.col.f32.f16.f16.f32 "
        "{%0,%1,%2,%3}, {%4,%5,%6,%7}, {%8,%9}, {%0,%1,%2,%3};"
        : "+f"(c[0]), "+f"(c[1]), "+f"(c[2]), "+f"(c[3])
        : "r"(a[0]), "r"(a[1]), "r"(a[2]), "r"(a[3]), "r"(b0), "r"(b1));
}
__device__ __forceinline__ float silu_f(float v) { return v / (1.f + expf(-v)); }

__device__ __forceinline__ uint32_t pack_h2(float a, float b) {
    __half2 h = __floats2half2_rn(a, b);
    return ((uint32_t)__half_as_ushort(__high2half(h)) << 16)
         | (uint32_t)__half_as_ushort(__low2half(h));
}

// ---------------- init / cvt -------------------------------------------------
__global__ void init_kernel() { if (threadIdx.x < EE) g_cnt[threadIdx.x] = 0; }

// merged prep: y=0..3 cvt (w1,w3,ws1,ws3); y=4 zero out
struct CvtArgs {
    const float* src[5];
    __half* dst[5];
    int n8[5];
    float* out;
    int out_n4;
};
__global__ void cvt_all_kernel(CvtArgs args) {
    const int y = blockIdx.y;
    if (y == 4) {
        float4* o = (float4*)args.out;
        int i = blockIdx.x * blockDim.x + threadIdx.x;
        const int stride = gridDim.x * blockDim.x;
        float4 z = make_float4(0.f, 0.f, 0.f, 0.f);
        for (; i < args.out_n4; i += stride) o[i] = z;
        return;
    }
    const float4* s = (const float4*)args.src[y];
    uint4* d = (uint4*)args.dst[y];
    const int n8 = args.n8[y];
    int i = blockIdx.x * blockDim.x + threadIdx.x;
    const int stride = gridDim.x * blockDim.x;
    for (; i < n8; i += stride) {
        float4 v0 = s[i * 2];
        float4 v1 = s[i * 2 + 1];
        uint4 o;
        o.x = pack_h2(v0.x, v0.y);
        o.y = pack_h2(v0.z, v0.w);
        o.z = pack_h2(v1.x, v1.y);
        o.w = pack_h2(v1.z, v1.w);
        d[i] = o;
    }
}

// ---------------- router: scores + top-2 + fp16 x copy (vectorized) ----------
__global__ void router_kernel(const float* __restrict__ x, const float* __restrict__ gw) {
    int warp = (blockIdx.x * blockDim.x + threadIdx.x) >> 5;
    int lane = threadIdx.x & 31;
    if (warp >= TT) return;
    const float* xr = x + (size_t)warp * DD;
    __half* xo = g_xh + (size_t)warp * DD;
    float acc[EE];
    #pragma unroll
    for (int e = 0; e < EE; e++) acc[e] = 0.f;
    for (int d0 = lane * 4; d0 < DD; d0 += 128) {
        float4 v = *(const float4*)(xr + d0);
        uint2 o;
        o.x = pack_h2(v.x, v.y);
        o.y = pack_h2(v.z, v.w);
        *(uint2*)(xo + d0) = o;
        float vv[4] = {v.x, v.y, v.z, v.w};
        #pragma unroll
        for (int j = 0; j < 4; j++) {
            const float* g = gw + (size_t)(d0 + j) * EE;
            #pragma unroll
            for (int e = 0; e < EE; e++) acc[e] += vv[j] * g[e];
        }
    }
    #pragma unroll
    for (int e = 0; e < EE; e++) {
        #pragma unroll
        for (int o = 16; o > 0; o >>= 1) acc[e] += __shfl_xor_sync(0xFFFFFFFFu, acc[e], o);
    }
    if (lane == 0) {
        float s[EE];
        #pragma unroll
        for (int e = 0; e < EE; e++) s[e] = 1.f / (1.f + expf(-acc[e]));
        int i0 = 0;
        #pragma unroll
        for (int e = 1; e < EE; e++) if (s[e] > s[i0]) i0 = e;
        int i1 = (i0 == 0) ? 1 : 0;
        #pragma unroll
        for (int e = 0; e < EE; e++) { if (e != i0 && s[e] > s[i1]) i1 = e; }
        float sum = s[i0] + s[i1];
        int p0 = atomicAdd(&g_cnt[i0], 1);
        g_tok[i0 * TT + p0] = warp; g_wt[i0 * TT + p0] = s[i0] / sum;
        int p1 = atomicAdd(&g_cnt[i1], 1);
        g_tok[i1 * TT + p1] = warp; g_wt[i1 * TT + p1] = s[i1] / sum;
    }
}

// ---------------- fused SwiGLU GEMM (fp16 mma + ldmatrix) --------------------
// BM=128, BN=64, BK=32, 256 threads, 8 warps = 4(m) x 2(n), warp tile 32x32.
// z==0: shared (A=g_xh, B=g_ws1h/g_ws3h ld HSS, C=g_hsh); z>=1: expert e=z-1.
// Idle CTAs (z>=1, blockIdx.x>=8) instead convert w2/ws2 to fp16 (overlapped).
__global__ __launch_bounds__(256, 2)
void glu_tc(const float* __restrict__ w2src, const float* __restrict__ ws2src) {
    extern __shared__ __half smh[];
    const int tid = threadIdx.x;
    const int z = blockIdx.z, e = z - 1;

    if (z >= 1 && blockIdx.x >= 8) {
        // ---- overlapped weight conversion for the down-proj launch ----
        const int NW2  = EE * HH * DD / 8;   // 524288 groups of 8 floats
        const int NWS2 = HSS * DD / 8;       // 131072
        int wq = (((z - 1) * 8 + ((int)blockIdx.x - 8)) * 16 + (int)blockIdx.y) * 256 + tid;
        const int wstride = 1024 * 256;
        for (int i = wq; i < NW2 + NWS2; i += wstride) {
            const float4* s;
            uint4* d;
            int j;
            if (i < NW2) { s = (const float4*)w2src;  d = (uint4*)g_w2h;  j = i; }
            else         { s = (const float4*)ws2src; d = (uint4*)g_ws2h; j = i - NW2; }
            float4 v0 = s[j * 2];
            float4 v1 = s[j * 2 + 1];
            uint4 o;
            o.x = pack_h2(v0.x, v0.y);
            o.y = pack_h2(v0.z, v0.w);
            o.z = pack_h2(v1.x, v1.y);
            o.w = pack_h2(v1.z, v1.w);
            d[j] = o;
        }
        return;
    }

    int M, ldB, ldC;
    const __half *B1, *B3;
    const int* tok = nullptr;
    __half* C;
    if (z == 0) {
        M = TT; ldB = HSS; ldC = HSS;
        B1 = g_ws1h; B3 = g_ws3h; C = g_hsh;
    } else {
        M = g_cnt[e]; ldB = HH; ldC = HH;
        tok = g_tok + e * TT;
        B1 = g_w1h + (size_t)e * DD * HH;
        B3 = g_w3h + (size_t)e * DD * HH;
        C  = g_hidh + (size_t)e * TT * HH;
    }
    const int m0 = blockIdx.y * 128, n0 = blockIdx.x * 64;
    if (m0 >= M) return;

    const uint32_t sb = smem_u32(smh);

    // producers: A 2 chunks (16B = 8 halves), B1/B3 1 chunk each, per stage
    const __half* aptr[2];
    uint32_t adst[2];
    #pragma unroll
    for (int i = 0; i < 2; i++) {
        int id = tid + i * 256;
        int am = id >> 2, ac = id & 3;                 // row 0..127, chunk 0..3
        int gm = m0 + am;
        int sr = (z == 0) ? gm : ((gm < M) ? tok[gm] : tok[m0]);
        aptr[i] = g_xh + (size_t)sr * DD + ac * 8;
        adst[i] = sb + (uint32_t)(am * 32 + ((ac ^ ((am >> 1) & 3)) * 8)) * 2;
    }
    const int bk = tid >> 3, bch = tid & 7;            // row 0..31, chunk 0..7
    const __half* b1p = B1 + (size_t)bk * ldB + n0 + bch * 8;
    const __half* b3p = B3 + (size_t)bk * ldB + n0 + bch * 8;
    const uint32_t bdst = sb + (uint32_t)(4096 + bk * 72 + bch * 8) * 2;

    const int nit = DD / BK;  // 32

    auto load_stage = [&](int it) {
        if (it < nit) {
            uint32_t so = (uint32_t)(it % NST) * GLU_STGH * 2;
            int k0 = it * BK;
            CP16(adst[0] + so, aptr[0] + k0);
            CP16(adst[1] + so, aptr[1] + k0);
            size_t wko = (size_t)k0 * ldB;
            CP16(bdst + so,            b1p + wko);
            CP16(bdst + so + 2304 * 2, b3p + wko);
        }
        CP_COMMIT();
    };

    const int lane = tid & 31, wid = tid >> 5;
    const int g = lane >> 2, t = lane & 3;
    const int wm = wid >> 1, wn = wid & 1;
    const int hi = lane >> 4;          // 0: k-lo half, 1: k-hi half

    // precompute per-lane ldmatrix byte offsets (within stage)
    uint32_t aoffb[2][2];              // [mf][s]
    #pragma unroll
    for (int mf = 0; mf < 2; mf++) {
        int row = wm * 32 + mf * 16 + (lane & 15);
        #pragma unroll
        for (int s = 0; s < 2; s++) {
            int chunk = (s * 2 + hi) ^ ((row >> 1) & 3);
            aoffb[mf][s] = (uint32_t)(row * 32 + chunk * 8) * 2;
        }
    }
    uint32_t boffb[2][2];              // [nt][s] (B1; B3 = +2304*2)
    #pragma unroll
    for (int nt = 0; nt < 2; nt++) {
        int n_off = wn * 32 + nt * 16 + hi * 8;
        #pragma unroll
        for (int s = 0; s < 2; s++) {
            int kl = s * 16 + ((lane >> 3) & 1) * 8 + (lane & 7);
            boffb[nt][s] = (uint32_t)(4096 + kl * 72 + n_off) * 2;
        }
    }

    float acc1[2][4][4] = {}, acc3[2][4][4] = {};

    for (int p = 0; p < NST - 1; p++) load_stage(p);

    for (int it = 0; it < nit; it++) {
        CP_WAIT2();
        __syncthreads();
        load_stage(it + NST - 1);
        uint32_t stb = sb + (uint32_t)(it % NST) * GLU_STGH * 2;
        #pragma unroll
        for (int s = 0; s < 2; s++) {
            uint32_t a[2][4], b1r[2][4], b3r[2][4];
            #pragma unroll
            for (int mf = 0; mf < 2; mf++)
                LDSM4(a[mf][0], a[mf][1], a[mf][2], a[mf][3], stb + aoffb[mf][s]);
            #pragma unroll
            for (int nt = 0; nt < 2; nt++) {
                LDSM4T(b1r[nt][0], b1r[nt][1], b1r[nt][2], b1r[nt][3], stb + boffb[nt][s]);
                LDSM4T(b3r[nt][0], b3r[nt][1], b3r[nt][2], b3r[nt][3], stb + boffb[nt][s] + 2304 * 2);
            }
            #pragma unroll
            for (int mf = 0; mf < 2; mf++)
                #pragma unroll
                for (int nf = 0; nf < 4; nf++) {
                    mmah(acc1[mf][nf], a[mf], b1r[nf >> 1][(nf & 1) * 2], b1r[nf >> 1][(nf & 1) * 2 + 1]);
                    mmah(acc3[mf][nf], a[mf], b3r[nf >> 1][(nf & 1) * 2], b3r[nf >> 1][(nf & 1) * 2 + 1]);
                }
        }
        __syncthreads();
    }

    // epilogue: C = fp16(silu(acc1) * acc3)
    #pragma unroll
    for (int mf = 0; mf < 2; mf++) {
        #pragma unroll
        for (int nf = 0; nf < 4; nf++) {
            int r0  = m0 + wm * 32 + mf * 16 + g;
            int col = n0 + wn * 32 + nf * 8 + t * 2;
            if (r0 < M) {
                uint32_t v = pack_h2(silu_f(acc1[mf][nf][0]) * acc3[mf][nf][0],
                                     silu_f(acc1[mf][nf][1]) * acc3[mf][nf][1]);
                *(uint32_t*)&C[(size_t)r0 * ldC + col] = v;
            }
            int r1 = r0 + 8;
            if (r1 < M) {
                uint32_t v = pack_h2(silu_f(acc1[mf][nf][2]) * acc3[mf][nf][2],
                                     silu_f(acc1[mf][nf][3]) * acc3[mf][nf][3]);
                *(uint32_t*)&C[(size_t)r1 * ldC + col] = v;
            }
        }
    }
}

// ---------------- merged down-proj GEMM (fp16 mma + ldmatrix) ----------------
// BM=128, BN=128, BK=32, 256 threads, 8 warps = 2(m) x 4(n), warp tile 64x32.
// z==0: shared (A=g_hsh, B=g_ws2h, w=1, token=m); z>=1: routed expert e=z-1
__global__ __launch_bounds__(256, 2)
void down_tc(float* __restrict__ out) {
    extern __shared__ __half smh[];
    const int tid = threadIdx.x;
    const int z = blockIdx.z, e = z - 1;

    int M, Kd;
    const __half *A, *B;
    if (z == 0) { M = TT; Kd = HSS; A = g_hsh; B = g_ws2h; }
    else {
        M = g_cnt[e]; Kd = HH;
        A = g_hidh + (size_t)e * TT * HH;
        B = g_w2h + (size_t)e * HH * DD;
    }
    const int m0 = blockIdx.y * 128, n0 = blockIdx.x * 128;
    if (m0 >= M) return;

    const uint32_t sb = smem_u32(smh);

    const __half* aptr[2];
    uint32_t adst[2];
    #pragma unroll
    for (int i = 0; i < 2; i++) {
        int id = tid + i * 256;
        int am = id >> 2, ac = id & 3;
        int r = m0 + am;
        if (r >= M) r = m0;
        aptr[i] = A + (size_t)r * Kd + ac * 8;
        adst[i] = sb + (uint32_t)(am * 32 + ((ac ^ ((am >> 1) & 3)) * 8)) * 2;
    }
    const __half* bptr[2];
    uint32_t bdst[2];
    #pragma unroll
    for (int i = 0; i < 2; i++) {
        int id = tid + i * 256;
        int k = id >> 4, nch = id & 15;                // row 0..31, chunk 0..15
        bptr[i] = B + (size_t)k * DD + n0 + nch * 8;
        bdst[i] = sb + (uint32_t)(4096 + k * 136 + nch * 8) * 2;
    }
    const int nit = Kd / BK;  // 32 or 16

    auto load_stage = [&](int it) {
        if (it < nit) {
            uint32_t so = (uint32_t)(it % NST) * DN_STGH * 2;
            int k0 = it * BK;
            CP16(adst[0] + so, aptr[0] + k0);
            CP16(adst[1] + so, aptr[1] + k0);
            size_t wko = (size_t)k0 * DD;
            CP16(bdst[0] + so, bptr[0] + wko);
            CP16(bdst[1] + so, bptr[1] + wko);
        }
        CP_COMMIT();
    };

    const int lane = tid & 31, wid = tid >> 5;
    const int g = lane >> 2, t = lane & 3;
    const int wm = wid >> 2, wn = wid & 3;
    const int hi = lane >> 4;

    uint32_t aoffb[4][2];              // [mf][s]
    #pragma unroll
    for (int mf = 0; mf < 4; mf++) {
        int row = wm * 64 + mf * 16 + (lane & 15);
        #pragma unroll
        for (int s = 0; s < 2; s++) {
            int chunk = (s * 2 + hi) ^ ((row >> 1) & 3);
            aoffb[mf][s] = (uint32_t)(row * 32 + chunk * 8) * 2;
        }
    }
    uint32_t boffb[2][2];              // [nt][s]
    #pragma unroll
    for (int nt = 0; nt < 2; nt++) {
        int n_off = wn * 32 + nt * 16 + hi * 8;
        #pragma unroll
        for (int s = 0; s < 2; s++) {
            int kl = s * 16 + ((lane >> 3) & 1) * 8 + (lane & 7);
            boffb[nt][s] = (uint32_t)(4096 + kl * 136 + n_off) * 2;
        }
    }

    float acc[4][4][4] = {};

    for (int p = 0; p < NST - 1; p++) load_stage(p);

    for (int it = 0; it < nit; it++) {
        CP_WAIT2();
        __syncthreads();
        load_stage(it + NST - 1);
        uint32_t stb = sb + (uint32_t)(it % NST) * DN_STGH * 2;
        #pragma unroll
        for (int s = 0; s < 2; s++) {
            uint32_t a[4][4], br[2][4];
            #pragma unroll
            for (int mf = 0; mf < 4; mf++)
                LDSM4(a[mf][0], a[mf][1], a[mf][2], a[mf][3], stb + aoffb[mf][s]);
            #pragma unroll
            for (int nt = 0; nt < 2; nt++)
                LDSM4T(br[nt][0], br[nt][1], br[nt][2], br[nt][3], stb + boffb[nt][s]);
            #pragma unroll
            for (int mf = 0; mf < 4; mf++)
                #pragma unroll
                for (int nf = 0; nf < 4; nf++)
                    mmah(acc[mf][nf], a[mf], br[nf >> 1][(nf & 1) * 2], br[nf >> 1][(nf & 1) * 2 + 1]);
        }
        __syncthreads();
    }

    #pragma unroll
    for (int mf = 0; mf < 4; mf++) {
        #pragma unroll
        for (int nf = 0; nf < 4; nf++) {
            int r0  = m0 + wm * 64 + mf * 16 + g;
            int col = n0 + wn * 32 + nf * 8 + t * 2;
            if (r0 < M) {
                int tk; float w;
                if (z == 0) { tk = r0; w = 1.f; }
                else        { tk = g_tok[e * TT + r0]; w = g_wt[e * TT + r0]; }
                float* orow = out + (size_t)tk * DD + col;
                atomicAdd(orow,     w * acc[mf][nf][0]);
                atomicAdd(orow + 1, w * acc[mf][nf][1]);
            }
            int r1 = r0 + 8;
            if (r1 < M) {
                int tk; float w;
                if (z == 0) { tk = r1; w = 1.f; }
                else        { tk = g_tok[e * TT + r1]; w = g_wt[e * TT + r1]; }
                float* orow = out + (size_t)tk * DD + col;
                atomicAdd(orow,     w * acc[mf][nf][2]);
                atomicAdd(orow + 1, w * acc[mf][nf][3]);
            }
        }
    }
}

// ---------------- launch -----------------------------------------------------
extern "C" void kernel_launch(void* const* d_in, const int* in_sizes, int n_in,
                              void* d_out, int out_size) {
    (void)in_sizes; (void)n_in; (void)out_size;
    const float* x   = (const float*)d_in[0];
    const float* gw  = (const float*)d_in[1];
    const float* w1  = (const float*)d_in[2];
    const float* w3  = (const float*)d_in[3];
    const float* w2  = (const float*)d_in[4];
    const float* ws1 = (const float*)d_in[5];
    const float* ws3 = (const float*)d_in[6];
    const float* ws2 = (const float*)d_in[7];
    float* out = (float*)d_out;

    cudaFuncSetAttribute(glu_tc,  cudaFuncAttributeMaxDynamicSharedMemorySize, GLU_SMEMB);
    cudaFuncSetAttribute(down_tc, cudaFuncAttributeMaxDynamicSharedMemorySize, DN_SMEMB);

    __half *w1h, *w3h, *ws1h, *ws3h;
    cudaGetSymbolAddress((void**)&w1h,  g_w1h);
    cudaGetSymbolAddress((void**)&w3h,  g_w3h);
    cudaGetSymbolAddress((void**)&ws1h, g_ws1h);
    cudaGetSymbolAddress((void**)&ws3h, g_ws3h);

    init_kernel<<<1, 32>>>();
    router_kernel<<<TT / 8, 256>>>(x, gw);

    CvtArgs ca;
    ca.src[0] = w1;  ca.dst[0] = w1h;  ca.n8[0] = EE * DD * HH / 8;
    ca.src[1] = w3;  ca.dst[1] = w3h;  ca.n8[1] = EE * DD * HH / 8;
    ca.src[2] = ws1; ca.dst[2] = ws1h; ca.n8[2] = DD * HSS / 8;
    ca.src[3] = ws3; ca.dst[3] = ws3h; ca.n8[3] = DD * HSS / 8;
    ca.src[4] = nullptr; ca.dst[4] = nullptr; ca.n8[4] = 0;
    ca.out = out;
    ca.out_n4 = TT * DD / 4;
    cvt_all_kernel<<<dim3(296, 5), 256>>>(ca);

    // fused SwiGLU: shared expert (z=0) + routed experts (z=1..8);
    // idle CTAs convert w2/ws2 in the background
    glu_tc<<<dim3(16, 16, 1 + EE), 256, GLU_SMEMB>>>(w2, ws2);

    // merged down-proj: all contributions atomically accumulated
    down_tc<<<dim3(8, 16, 1 + EE), 256, DN_SMEMB>>>(out);
}

// round 14
// speedup vs baseline: 1.0382x; 1.0382x over previous
#include <cuda_runtime.h>
#include <cuda_fp16.h>
#include <math.h>
#include <stdint.h>

#define TT  2048
#define DD  1024
#define HH  512
#define HSS 1024
#define EE  8
#define BK  32
#define NST 4

// stage sizes in halves
#define GLU_STGH 8704                  // A 128x32 = 4096, B1 32x72 = 2304, B3 2304
#define GLU_SMEMB (NST * GLU_STGH * 2) // 69632 B
#define DN_STGH  8448                  // A 4096, B 32x136 = 4352
#define DN_SMEMB  (NST * DN_STGH * 2)  // 67584 B

// ---------------- scratch ----------------------------------------------------
__device__ __half g_xh  [(size_t)TT * DD];        // fp16 input
__device__ __half g_hsh [(size_t)TT * HSS];       // fp16 shared hidden
__device__ __half g_hidh[(size_t)EE * TT * HH];   // fp16 routed hidden
__device__ __half g_w1h [(size_t)EE * DD * HH];
__device__ __half g_w3h [(size_t)EE * DD * HH];
__device__ __half g_w2h [(size_t)EE * HH * DD];
__device__ __half g_ws1h[(size_t)DD * HSS];
__device__ __half g_ws3h[(size_t)DD * HSS];
__device__ __half g_ws2h[(size_t)HSS * DD];
__device__ int    g_cnt[EE];
__device__ int    g_tok[EE * TT];
__device__ float  g_wt [EE * TT];

// ---------------- helpers ----------------------------------------------------
__device__ __forceinline__ uint32_t smem_u32(const void* p) {
    uint32_t a;
    asm("{ .reg .u64 t; cvta.to.shared.u64 t, %1; cvt.u32.u64 %0, t; }" : "=r"(a) : "l"(p));
    return a;
}
#define CP16(dst, src) \
    asm volatile("cp.async.cg.shared.global [%0], [%1], 16;" :: "r"((uint32_t)(dst)), "l"(src))
#define CP_COMMIT() asm volatile("cp.async.commit_group;" ::: "memory")
#define CP_WAIT2()  asm volatile("cp.async.wait_group 2;" ::: "memory")

#define LDSM4(r0, r1, r2, r3, addr) \
    asm volatile("ldmatrix.sync.aligned.m8n8.x4.shared.b16 {%0,%1,%2,%3}, [%4];" \
        : "=r"(r0), "=r"(r1), "=r"(r2), "=r"(r3) : "r"(addr))
#define LDSM4T(r0, r1, r2, r3, addr) \
    asm volatile("ldmatrix.sync.aligned.m8n8.x4.trans.shared.b16 {%0,%1,%2,%3}, [%4];" \
        : "=r"(r0), "=r"(r1), "=r"(r2), "=r"(r3) : "r"(addr))

__device__ __forceinline__ void mmah(float* c, const uint32_t* a, uint32_t b0, uint32_t b1) {
    asm volatile(
        "mma.sync.aligned.m16n8k16.row.col.f32.f16.f16.f32 "
        "{%0,%1,%2,%3}, {%4,%5,%6,%7}, {%8,%9}, {%0,%1,%2,%3};"
        : "+f"(c[0]), "+f"(c[1]), "+f"(c[2]), "+f"(c[3])
        : "r"(a[0]), "r"(a[1]), "r"(a[2]), "r"(a[3]), "r"(b0), "r"(b1));
}
__device__ __forceinline__ float silu_f(float v) { return v / (1.f + expf(-v)); }

__device__ __forceinline__ uint32_t pack_h2(float a, float b) {
    __half2 h = __floats2half2_rn(a, b);
    return ((uint32_t)__half_as_ushort(__high2half(h)) << 16)
         | (uint32_t)__half_as_ushort(__low2half(h));
}

// ---------------- init / prep ------------------------------------------------
__global__ void init_kernel() { if (threadIdx.x < EE) g_cnt[threadIdx.x] = 0; }

// balanced prep: y=0..2 cvt big weights (w1,w3,w2; 16MB each);
// y=3: ws1+ws3+ws2 cvt (4MB each) + zero out (8MB), concatenated.
struct PrepArgs {
    const float* big[3];
    __half* bigd[3];
    const float* ws1; const float* ws3; const float* ws2;
    float* out;
};
#define NBIG (EE * DD * HH / 8)     // 524288 groups of 8 floats
#define NSML (DD * HSS / 8)         // 131072
#define NOUT (TT * DD / 8)          // 262144 (zero: 32B per group)
__global__ void prep_kernel(PrepArgs args) {
    const int y = blockIdx.y;
    int i = blockIdx.x * blockDim.x + threadIdx.x;
    const int stride = gridDim.x * blockDim.x;
    if (y < 3) {
        const float4* s = (const float4*)args.big[y];
        uint4* d = (uint4*)args.bigd[y];
        for (; i < NBIG; i += stride) {
            float4 v0 = s[i * 2];
            float4 v1 = s[i * 2 + 1];
            uint4 o;
            o.x = pack_h2(v0.x, v0.y);
            o.y = pack_h2(v0.z, v0.w);
            o.z = pack_h2(v1.x, v1.y);
            o.w = pack_h2(v1.z, v1.w);
            d[i] = o;
        }
        return;
    }
    const int NTOT = 3 * NSML + NOUT;
    for (; i < NTOT; i += stride) {
        if (i < 3 * NSML) {
            const float4* s;
            uint4* d;
            int j;
            if (i < NSML)          { s = (const float4*)args.ws1; d = (uint4*)g_ws1h; j = i; }
            else if (i < 2 * NSML) { s = (const float4*)args.ws3; d = (uint4*)g_ws3h; j = i - NSML; }
            else                   { s = (const float4*)args.ws2; d = (uint4*)g_ws2h; j = i - 2 * NSML; }
            float4 v0 = s[j * 2];
            float4 v1 = s[j * 2 + 1];
            uint4 o;
            o.x = pack_h2(v0.x, v0.y);
            o.y = pack_h2(v0.z, v0.w);
            o.z = pack_h2(v1.x, v1.y);
            o.w = pack_h2(v1.z, v1.w);
            d[j] = o;
        } else {
            int j = i - 3 * NSML;
            float4 z = make_float4(0.f, 0.f, 0.f, 0.f);
            ((float4*)args.out)[j * 2]     = z;
            ((float4*)args.out)[j * 2 + 1] = z;
        }
    }
}

// ---------------- router: scores + top-2 + fp16 x copy (vectorized) ----------
__global__ void router_kernel(const float* __restrict__ x, const float* __restrict__ gw) {
    int warp = (blockIdx.x * blockDim.x + threadIdx.x) >> 5;
    int lane = threadIdx.x & 31;
    if (warp >= TT) return;
    const float* xr = x + (size_t)warp * DD;
    __half* xo = g_xh + (size_t)warp * DD;
    float acc[EE];
    #pragma unroll
    for (int e = 0; e < EE; e++) acc[e] = 0.f;
    for (int d0 = lane * 4; d0 < DD; d0 += 128) {
        float4 v = *(const float4*)(xr + d0);
        uint2 o;
        o.x = pack_h2(v.x, v.y);
        o.y = pack_h2(v.z, v.w);
        *(uint2*)(xo + d0) = o;
        float vv[4] = {v.x, v.y, v.z, v.w};
        #pragma unroll
        for (int j = 0; j < 4; j++) {
            const float* g = gw + (size_t)(d0 + j) * EE;
            #pragma unroll
            for (int e = 0; e < EE; e++) acc[e] += vv[j] * g[e];
        }
    }
    #pragma unroll
    for (int e = 0; e < EE; e++) {
        #pragma unroll
        for (int o = 16; o > 0; o >>= 1) acc[e] += __shfl_xor_sync(0xFFFFFFFFu, acc[e], o);
    }
    if (lane == 0) {
        float s[EE];
        #pragma unroll
        for (int e = 0; e < EE; e++) s[e] = 1.f / (1.f + expf(-acc[e]));
        int i0 = 0;
        #pragma unroll
        for (int e = 1; e < EE; e++) if (s[e] > s[i0]) i0 = e;
        int i1 = (i0 == 0) ? 1 : 0;
        #pragma unroll
        for (int e = 0; e < EE; e++) { if (e != i0 && s[e] > s[i1]) i1 = e; }
        float sum = s[i0] + s[i1];
        int p0 = atomicAdd(&g_cnt[i0], 1);
        g_tok[i0 * TT + p0] = warp; g_wt[i0 * TT + p0] = s[i0] / sum;
        int p1 = atomicAdd(&g_cnt[i1], 1);
        g_tok[i1 * TT + p1] = warp; g_wt[i1 * TT + p1] = s[i1] / sum;
    }
}

// ---------------- fused SwiGLU GEMM (fp16 mma + ldmatrix) --------------------
// BM=128, BN=64, BK=32, 256 threads, 8 warps = 4(m) x 2(n), warp tile 32x32.
// z==0: shared (A=g_xh, B=g_ws1h/g_ws3h ld HSS, C=g_hsh); z>=1: expert e=z-1
__global__ __launch_bounds__(256, 2)
void glu_tc() {
    extern __shared__ __half smh[];
    const int tid = threadIdx.x;
    const int z = blockIdx.z, e = z - 1;

    int M, ldB, ldC;
    const __half *B1, *B3;
    const int* tok = nullptr;
    __half* C;
    if (z == 0) {
        M = TT; ldB = HSS; ldC = HSS;
        B1 = g_ws1h; B3 = g_ws3h; C = g_hsh;
    } else {
        if (blockIdx.x >= HH / 64) return;
        M = g_cnt[e]; ldB = HH; ldC = HH;
        tok = g_tok + e * TT;
        B1 = g_w1h + (size_t)e * DD * HH;
        B3 = g_w3h + (size_t)e * DD * HH;
        C  = g_hidh + (size_t)e * TT * HH;
    }
    const int m0 = blockIdx.y * 128, n0 = blockIdx.x * 64;
    if (m0 >= M) return;

    const uint32_t sb = smem_u32(smh);

    // producers: A 2 chunks (16B = 8 halves), B1/B3 1 chunk each, per stage
    const __half* aptr[2];
    uint32_t adst[2];
    #pragma unroll
    for (int i = 0; i < 2; i++) {
        int id = tid + i * 256;
        int am = id >> 2, ac = id & 3;                 // row 0..127, chunk 0..3
        int gm = m0 + am;
        int sr = (z == 0) ? gm : ((gm < M) ? tok[gm] : tok[m0]);
        aptr[i] = g_xh + (size_t)sr * DD + ac * 8;
        adst[i] = sb + (uint32_t)(am * 32 + ((ac ^ ((am >> 1) & 3)) * 8)) * 2;
    }
    const int bk = tid >> 3, bch = tid & 7;            // row 0..31, chunk 0..7
    const __half* b1p = B1 + (size_t)bk * ldB + n0 + bch * 8;
    const __half* b3p = B3 + (size_t)bk * ldB + n0 + bch * 8;
    const uint32_t bdst = sb + (uint32_t)(4096 + bk * 72 + bch * 8) * 2;

    const int nit = DD / BK;  // 32

    auto load_stage = [&](int it) {
        if (it < nit) {
            uint32_t so = (uint32_t)(it % NST) * GLU_STGH * 2;
            int k0 = it * BK;
            CP16(adst[0] + so, aptr[0] + k0);
            CP16(adst[1] + so, aptr[1] + k0);
            size_t wko = (size_t)k0 * ldB;
            CP16(bdst + so,            b1p + wko);
            CP16(bdst + so + 2304 * 2, b3p + wko);
        }
        CP_COMMIT();
    };

    const int lane = tid & 31, wid = tid >> 5;
    const int g = lane >> 2, t = lane & 3;
    const int wm = wid >> 1, wn = wid & 1;
    const int hi = lane >> 4;          // 0: k-lo half, 1: k-hi half

    // precompute per-lane ldmatrix byte offsets (within stage)
    uint32_t aoffb[2][2];              // [mf][s]
    #pragma unroll
    for (int mf = 0; mf < 2; mf++) {
        int row = wm * 32 + mf * 16 + (lane & 15);
        #pragma unroll
        for (int s = 0; s < 2; s++) {
            int chunk = (s * 2 + hi) ^ ((row >> 1) & 3);
            aoffb[mf][s] = (uint32_t)(row * 32 + chunk * 8) * 2;
        }
    }
    uint32_t boffb[2][2];              // [nt][s] (B1; B3 = +2304*2)
    #pragma unroll
    for (int nt = 0; nt < 2; nt++) {
        int n_off = wn * 32 + nt * 16 + hi * 8;
        #pragma unroll
        for (int s = 0; s < 2; s++) {
            int kl = s * 16 + ((lane >> 3) & 1) * 8 + (lane & 7);
            boffb[nt][s] = (uint32_t)(4096 + kl * 72 + n_off) * 2;
        }
    }

    float acc1[2][4][4] = {}, acc3[2][4][4] = {};

    for (int p = 0; p < NST - 1; p++) load_stage(p);

    for (int it = 0; it < nit; it++) {
        CP_WAIT2();
        __syncthreads();
        load_stage(it + NST - 1);
        uint32_t stb = sb + (uint32_t)(it % NST) * GLU_STGH * 2;
        #pragma unroll
        for (int s = 0; s < 2; s++) {
            uint32_t a[2][4], b1r[2][4], b3r[2][4];
            #pragma unroll
            for (int mf = 0; mf < 2; mf++)
                LDSM4(a[mf][0], a[mf][1], a[mf][2], a[mf][3], stb + aoffb[mf][s]);
            #pragma unroll
            for (int nt = 0; nt < 2; nt++) {
                LDSM4T(b1r[nt][0], b1r[nt][1], b1r[nt][2], b1r[nt][3], stb + boffb[nt][s]);
                LDSM4T(b3r[nt][0], b3r[nt][1], b3r[nt][2], b3r[nt][3], stb + boffb[nt][s] + 2304 * 2);
            }
            #pragma unroll
            for (int mf = 0; mf < 2; mf++)
                #pragma unroll
                for (int nf = 0; nf < 4; nf++) {
                    mmah(acc1[mf][nf], a[mf], b1r[nf >> 1][(nf & 1) * 2], b1r[nf >> 1][(nf & 1) * 2 + 1]);
                    mmah(acc3[mf][nf], a[mf], b3r[nf >> 1][(nf & 1) * 2], b3r[nf >> 1][(nf & 1) * 2 + 1]);
                }
        }
        __syncthreads();
    }

    // epilogue: C = fp16(silu(acc1) * acc3)
    #pragma unroll
    for (int mf = 0; mf < 2; mf++) {
        #pragma unroll
        for (int nf = 0; nf < 4; nf++) {
            int r0  = m0 + wm * 32 + mf * 16 + g;
            int col = n0 + wn * 32 + nf * 8 + t * 2;
            if (r0 < M) {
                uint32_t v = pack_h2(silu_f(acc1[mf][nf][0]) * acc3[mf][nf][0],
                                     silu_f(acc1[mf][nf][1]) * acc3[mf][nf][1]);
                *(uint32_t*)&C[(size_t)r0 * ldC + col] = v;
            }
            int r1 = r0 + 8;
            if (r1 < M) {
                uint32_t v = pack_h2(silu_f(acc1[mf][nf][2]) * acc3[mf][nf][2],
                                     silu_f(acc1[mf][nf][3]) * acc3[mf][nf][3]);
                *(uint32_t*)&C[(size_t)r1 * ldC + col] = v;
            }
        }
    }
}

// ---------------- merged down-proj GEMM (fp16 mma + ldmatrix) ----------------
// BM=128, BN=128, BK=32, 256 threads, 8 warps = 2(m) x 4(n), warp tile 64x32.
// z==0: shared (A=g_hsh, B=g_ws2h, w=1, token=m); z>=1: routed expert e=z-1
__global__ __launch_bounds__(256, 2)
void down_tc(float* __restrict__ out) {
    extern __shared__ __half smh[];
    const int tid = threadIdx.x;
    const int z = blockIdx.z, e = z - 1;

    int M, Kd;
    const __half *A, *B;
    if (z == 0) { M = TT; Kd = HSS; A = g_hsh; B = g_ws2h; }
    else {
        M = g_cnt[e]; Kd = HH;
        A = g_hidh + (size_t)e * TT * HH;
        B = g_w2h + (size_t)e * HH * DD;
    }
    const int m0 = blockIdx.y * 128, n0 = blockIdx.x * 128;
    if (m0 >= M) return;

    const uint32_t sb = smem_u32(smh);

    const __half* aptr[2];
    uint32_t adst[2];
    #pragma unroll
    for (int i = 0; i < 2; i++) {
        int id = tid + i * 256;
        int am = id >> 2, ac = id & 3;
        int r = m0 + am;
        if (r >= M) r = m0;
        aptr[i] = A + (size_t)r * Kd + ac * 8;
        adst[i] = sb + (uint32_t)(am * 32 + ((ac ^ ((am >> 1) & 3)) * 8)) * 2;
    }
    const __half* bptr[2];
    uint32_t bdst[2];
    #pragma unroll
    for (int i = 0; i < 2; i++) {
        int id = tid + i * 256;
        int k = id >> 4, nch = id & 15;                // row 0..31, chunk 0..15
        bptr[i] = B + (size_t)k * DD + n0 + nch * 8;
        bdst[i] = sb + (uint32_t)(4096 + k * 136 + nch * 8) * 2;
    }
    const int nit = Kd / BK;  // 32 or 16

    auto load_stage = [&](int it) {
        if (it < nit) {
            uint32_t so = (uint32_t)(it % NST) * DN_STGH * 2;
            int k0 = it * BK;
            CP16(adst[0] + so, aptr[0] + k0);
            CP16(adst[1] + so, aptr[1] + k0);
            size_t wko = (size_t)k0 * DD;
            CP16(bdst[0] + so, bptr[0] + wko);
            CP16(bdst[1] + so, bptr[1] + wko);
        }
        CP_COMMIT();
    };

    const int lane = tid & 31, wid = tid >> 5;
    const int g = lane >> 2, t = lane & 3;
    const int wm = wid >> 2, wn = wid & 3;
    const int hi = lane >> 4;

    uint32_t aoffb[4][2];              // [mf][s]
    #pragma unroll
    for (int mf = 0; mf < 4; mf++) {
        int row = wm * 64 + mf * 16 + (lane & 15);
        #pragma unroll
        for (int s = 0; s < 2; s++) {
            int chunk = (s * 2 + hi) ^ ((row >> 1) & 3);
            aoffb[mf][s] = (uint32_t)(row * 32 + chunk * 8) * 2;
        }
    }
    uint32_t boffb[2][2];              // [nt][s]
    #pragma unroll
    for (int nt = 0; nt < 2; nt++) {
        int n_off = wn * 32 + nt * 16 + hi * 8;
        #pragma unroll
        for (int s = 0; s < 2; s++) {
            int kl = s * 16 + ((lane >> 3) & 1) * 8 + (lane & 7);
            boffb[nt][s] = (uint32_t)(4096 + kl * 136 + n_off) * 2;
        }
    }

    float acc[4][4][4] = {};

    for (int p = 0; p < NST - 1; p++) load_stage(p);

    for (int it = 0; it < nit; it++) {
        CP_WAIT2();
        __syncthreads();
        load_stage(it + NST - 1);
        uint32_t stb = sb + (uint32_t)(it % NST) * DN_STGH * 2;
        #pragma unroll
        for (int s = 0; s < 2; s++) {
            uint32_t a[4][4], br[2][4];
            #pragma unroll
            for (int mf = 0; mf < 4; mf++)
                LDSM4(a[mf][0], a[mf][1], a[mf][2], a[mf][3], stb + aoffb[mf][s]);
            #pragma unroll
            for (int nt = 0; nt < 2; nt++)
                LDSM4T(br[nt][0], br[nt][1], br[nt][2], br[nt][3], stb + boffb[nt][s]);
            #pragma unroll
            for (int mf = 0; mf < 4; mf++)
                #pragma unroll
                for (int nf = 0; nf < 4; nf++)
                    mmah(acc[mf][nf], a[mf], br[nf >> 1][(nf & 1) * 2], br[nf >> 1][(nf & 1) * 2 + 1]);
        }
        __syncthreads();
    }

    #pragma unroll
    for (int mf = 0; mf < 4; mf++) {
        #pragma unroll
        for (int nf = 0; nf < 4; nf++) {
            int r0  = m0 + wm * 64 + mf * 16 + g;
            int col = n0 + wn * 32 + nf * 8 + t * 2;
            if (r0 < M) {
                int tk; float w;
                if (z == 0) { tk = r0; w = 1.f; }
                else        { tk = g_tok[e * TT + r0]; w = g_wt[e * TT + r0]; }
                float* orow = out + (size_t)tk * DD + col;
                atomicAdd(orow,     w * acc[mf][nf][0]);
                atomicAdd(orow + 1, w * acc[mf][nf][1]);
            }
            int r1 = r0 + 8;
            if (r1 < M) {
                int tk; float w;
                if (z == 0) { tk = r1; w = 1.f; }
                else        { tk = g_tok[e * TT + r1]; w = g_wt[e * TT + r1]; }
                float* orow = out + (size_t)tk * DD + col;
                atomicAdd(orow,     w * acc[mf][nf][2]);
                atomicAdd(orow + 1, w * acc[mf][nf][3]);
            }
        }
    }
}

// ---------------- launch -----------------------------------------------------
extern "C" void kernel_launch(void* const* d_in, const int* in_sizes, int n_in,
                              void* d_out, int out_size) {
    (void)in_sizes; (void)n_in; (void)out_size;
    const float* x   = (const float*)d_in[0];
    const float* gw  = (const float*)d_in[1];
    const float* w1  = (const float*)d_in[2];
    const float* w3  = (const float*)d_in[3];
    const float* w2  = (const float*)d_in[4];
    const float* ws1 = (const float*)d_in[5];
    const float* ws3 = (const float*)d_in[6];
    const float* ws2 = (const float*)d_in[7];
    float* out = (float*)d_out;

    cudaFuncSetAttribute(glu_tc,  cudaFuncAttributeMaxDynamicSharedMemorySize, GLU_SMEMB);
    cudaFuncSetAttribute(down_tc, cudaFuncAttributeMaxDynamicSharedMemorySize, DN_SMEMB);

    __half *w1h, *w3h, *w2h;
    cudaGetSymbolAddress((void**)&w1h, g_w1h);
    cudaGetSymbolAddress((void**)&w3h, g_w3h);
    cudaGetSymbolAddress((void**)&w2h, g_w2h);

    init_kernel<<<1, 32>>>();
    router_kernel<<<TT / 8, 256>>>(x, gw);

    PrepArgs pa;
    pa.big[0] = w1; pa.bigd[0] = w1h;
    pa.big[1] = w3; pa.bigd[1] = w3h;
    pa.big[2] = w2; pa.bigd[2] = w2h;
    pa.ws1 = ws1; pa.ws3 = ws3; pa.ws2 = ws2;
    pa.out = out;
    prep_kernel<<<dim3(296, 4), 256>>>(pa);

    // fused SwiGLU: shared expert (z=0) + routed experts (z=1..8)
    glu_tc<<<dim3(16, 16, 1 + EE), 256, GLU_SMEMB>>>();

    // merged down-proj: all contributions atomically accumulated
    down_tc<<<dim3(8, 16, 1 + EE), 256, DN_SMEMB>>>(out);
}

// round 15
// speedup vs baseline: 1.0404x; 1.0021x over previous
#include <cuda_runtime.h>
#include <cuda_fp16.h>
#include <math.h>
#include <stdint.h>

#define TT  2048
#define DD  1024
#define HH  512
#define HSS 1024
#define EE  8
#define BK  32
#define NST 4

// stage sizes in halves
#define GLU_STGH 8704                  // A 128x32 = 4096, B1 32x72 = 2304, B3 2304
#define GLU_SMEMB (NST * GLU_STGH * 2) // 69632 B
#define DN_STGH  8448                  // A 4096, B 32x136 = 4352
#define DN_SMEMB  (NST * DN_STGH * 2)  // 67584 B

// ---------------- scratch ----------------------------------------------------
__device__ __half g_xh  [(size_t)TT * DD];        // fp16 input
__device__ __half g_hsh [(size_t)TT * HSS];       // fp16 shared hidden
__device__ __half g_hidh[(size_t)EE * TT * HH];   // fp16 routed hidden
__device__ __half g_w1h [(size_t)EE * DD * HH];
__device__ __half g_w3h [(size_t)EE * DD * HH];
__device__ __half g_w2h [(size_t)EE * HH * DD];
__device__ __half g_ws1h[(size_t)DD * HSS];
__device__ __half g_ws3h[(size_t)DD * HSS];
__device__ __half g_ws2h[(size_t)HSS * DD];
__device__ int    g_cnt[EE];
__device__ int    g_tok[EE * TT];
__device__ float  g_wt [EE * TT];

// ---------------- helpers ----------------------------------------------------
__device__ __forceinline__ uint32_t smem_u32(const void* p) {
    uint32_t a;
    asm("{ .reg .u64 t; cvta.to.shared.u64 t, %1; cvt.u32.u64 %0, t; }" : "=r"(a) : "l"(p));
    return a;
}
#define CP16(dst, src) \
    asm volatile("cp.async.cg.shared.global [%0], [%1], 16;" :: "r"((uint32_t)(dst)), "l"(src))
#define CP_COMMIT() asm volatile("cp.async.commit_group;" ::: "memory")
#define CP_WAIT2()  asm volatile("cp.async.wait_group 2;" ::: "memory")

#define LDSM4(r0, r1, r2, r3, addr) \
    asm volatile("ldmatrix.sync.aligned.m8n8.x4.shared.b16 {%0,%1,%2,%3}, [%4];" \
        : "=r"(r0), "=r"(r1), "=r"(r2), "=r"(r3) : "r"(addr))
#define LDSM4T(r0, r1, r2, r3, addr) \
    asm volatile("ldmatrix.sync.aligned.m8n8.x4.trans.shared.b16 {%0,%1,%2,%3}, [%4];" \
        : "=r"(r0), "=r"(r1), "=r"(r2), "=r"(r3) : "r"(addr))

__device__ __forceinline__ void mmah(float* c, const uint32_t* a, uint32_t b0, uint32_t b1) {
    asm volatile(
        "mma.sync.aligned.m16n8k16.row.col.f32.f16.f16.f32 "
        "{%0,%1,%2,%3}, {%4,%5,%6,%7}, {%8,%9}, {%0,%1,%2,%3};"
        : "+f"(c[0]), "+f"(c[1]), "+f"(c[2]), "+f"(c[3])
        : "r"(a[0]), "r"(a[1]), "r"(a[2]), "r"(a[3]), "r"(b0), "r"(b1));
}
__device__ __forceinline__ float silu_f(float v) { return v / (1.f + expf(-v)); }

__device__ __forceinline__ uint32_t pack_h2(float a, float b) {
    __half2 h = __floats2half2_rn(a, b);
    return ((uint32_t)__half_as_ushort(__high2half(h)) << 16)
         | (uint32_t)__half_as_ushort(__low2half(h));
}

// ---------------- init / prep ------------------------------------------------
__global__ void init_kernel() { if (threadIdx.x < EE) g_cnt[threadIdx.x] = 0; }

// balanced prep: y=0..2 cvt big weights (w1,w3,w2; 16MB each);
// y=3: ws1+ws3+ws2 cvt (4MB each) + zero out (8MB), concatenated.
struct PrepArgs {
    const float* big[3];
    __half* bigd[3];
    const float* ws1; const float* ws3; const float* ws2;
    float* out;
};
#define NBIG (EE * DD * HH / 8)     // 524288 groups of 8 floats
#define NSML (DD * HSS / 8)         // 131072
#define NOUT (TT * DD / 8)          // 262144 (zero: 32B per group)
__global__ void prep_kernel(PrepArgs args) {
    const int y = blockIdx.y;
    int i = blockIdx.x * blockDim.x + threadIdx.x;
    const int stride = gridDim.x * blockDim.x;
    if (y < 3) {
        const float4* s = (const float4*)args.big[y];
        uint4* d = (uint4*)args.bigd[y];
        for (; i < NBIG; i += stride) {
            float4 v0 = s[i * 2];
            float4 v1 = s[i * 2 + 1];
            uint4 o;
            o.x = pack_h2(v0.x, v0.y);
            o.y = pack_h2(v0.z, v0.w);
            o.z = pack_h2(v1.x, v1.y);
            o.w = pack_h2(v1.z, v1.w);
            d[i] = o;
        }
        return;
    }
    const int NTOT = 3 * NSML + NOUT;
    for (; i < NTOT; i += stride) {
        if (i < 3 * NSML) {
            const float4* s;
            uint4* d;
            int j;
            if (i < NSML)          { s = (const float4*)args.ws1; d = (uint4*)g_ws1h; j = i; }
            else if (i < 2 * NSML) { s = (const float4*)args.ws3; d = (uint4*)g_ws3h; j = i - NSML; }
            else                   { s = (const float4*)args.ws2; d = (uint4*)g_ws2h; j = i - 2 * NSML; }
            float4 v0 = s[j * 2];
            float4 v1 = s[j * 2 + 1];
            uint4 o;
            o.x = pack_h2(v0.x, v0.y);
            o.y = pack_h2(v0.z, v0.w);
            o.z = pack_h2(v1.x, v1.y);
            o.w = pack_h2(v1.z, v1.w);
            d[j] = o;
        } else {
            int j = i - 3 * NSML;
            float4 z = make_float4(0.f, 0.f, 0.f, 0.f);
            ((float4*)args.out)[j * 2]     = z;
            ((float4*)args.out)[j * 2 + 1] = z;
        }
    }
}

// ---------------- router: scores + top-2 + fp16 x copy (vectorized) ----------
__global__ void router_kernel(const float* __restrict__ x, const float* __restrict__ gw) {
    int warp = (blockIdx.x * blockDim.x + threadIdx.x) >> 5;
    int lane = threadIdx.x & 31;
    if (warp >= TT) return;
    const float* xr = x + (size_t)warp * DD;
    __half* xo = g_xh + (size_t)warp * DD;
    float acc[EE];
    #pragma unroll
    for (int e = 0; e < EE; e++) acc[e] = 0.f;
    for (int d0 = lane * 4; d0 < DD; d0 += 128) {
        float4 v = *(const float4*)(xr + d0);
        uint2 o;
        o.x = pack_h2(v.x, v.y);
        o.y = pack_h2(v.z, v.w);
        *(uint2*)(xo + d0) = o;
        float vv[4] = {v.x, v.y, v.z, v.w};
        #pragma unroll
        for (int j = 0; j < 4; j++) {
            const float* g = gw + (size_t)(d0 + j) * EE;
            #pragma unroll
            for (int e = 0; e < EE; e++) acc[e] += vv[j] * g[e];
        }
    }
    #pragma unroll
    for (int e = 0; e < EE; e++) {
        #pragma unroll
        for (int o = 16; o > 0; o >>= 1) acc[e] += __shfl_xor_sync(0xFFFFFFFFu, acc[e], o);
    }
    if (lane == 0) {
        float s[EE];
        #pragma unroll
        for (int e = 0; e < EE; e++) s[e] = 1.f / (1.f + expf(-acc[e]));
        int i0 = 0;
        #pragma unroll
        for (int e = 1; e < EE; e++) if (s[e] > s[i0]) i0 = e;
        int i1 = (i0 == 0) ? 1 : 0;
        #pragma unroll
        for (int e = 0; e < EE; e++) { if (e != i0 && s[e] > s[i1]) i1 = e; }
        float sum = s[i0] + s[i1];
        int p0 = atomicAdd(&g_cnt[i0], 1);
        g_tok[i0 * TT + p0] = warp; g_wt[i0 * TT + p0] = s[i0] / sum;
        int p1 = atomicAdd(&g_cnt[i1], 1);
        g_tok[i1 * TT + p1] = warp; g_wt[i1 * TT + p1] = s[i1] / sum;
    }
}

// ---------------- fused SwiGLU GEMM (fp16 mma + ldmatrix) --------------------
// BM=128, BN=64, BK=32, 256 threads, 8 warps = 4(m) x 2(n), warp tile 32x32.
// z==0: shared (A=g_xh, B=g_ws1h/g_ws3h ld HSS, C=g_hsh); z>=1: expert e=z-1
__global__ __launch_bounds__(256, 2)
void glu_tc() {
    extern __shared__ __half smh[];
    const int tid = threadIdx.x;
    const int z = blockIdx.z, e = z - 1;

    int M, ldB, ldC;
    const __half *B1, *B3;
    const int* tok = nullptr;
    __half* C;
    if (z == 0) {
        M = TT; ldB = HSS; ldC = HSS;
        B1 = g_ws1h; B3 = g_ws3h; C = g_hsh;
    } else {
        if (blockIdx.x >= HH / 64) return;
        M = g_cnt[e]; ldB = HH; ldC = HH;
        tok = g_tok + e * TT;
        B1 = g_w1h + (size_t)e * DD * HH;
        B3 = g_w3h + (size_t)e * DD * HH;
        C  = g_hidh + (size_t)e * TT * HH;
    }
    const int m0 = blockIdx.y * 128, n0 = blockIdx.x * 64;
    if (m0 >= M) return;

    const uint32_t sb = smem_u32(smh);

    // producers: A 2 chunks (16B = 8 halves), B1/B3 1 chunk each, per stage
    const __half* aptr[2];
    uint32_t adst[2];
    #pragma unroll
    for (int i = 0; i < 2; i++) {
        int id = tid + i * 256;
        int am = id >> 2, ac = id & 3;                 // row 0..127, chunk 0..3
        int gm = m0 + am;
        int sr = (z == 0) ? gm : ((gm < M) ? tok[gm] : tok[m0]);
        aptr[i] = g_xh + (size_t)sr * DD + ac * 8;
        adst[i] = sb + (uint32_t)(am * 32 + ((ac ^ ((am >> 1) & 3)) * 8)) * 2;
    }
    const int bk = tid >> 3, bch = tid & 7;            // row 0..31, chunk 0..7
    const __half* b1p = B1 + (size_t)bk * ldB + n0 + bch * 8;
    const __half* b3p = B3 + (size_t)bk * ldB + n0 + bch * 8;
    const uint32_t bdst = sb + (uint32_t)(4096 + bk * 72 + bch * 8) * 2;

    const int nit = DD / BK;  // 32

    auto load_stage = [&](int it) {
        if (it < nit) {
            uint32_t so = (uint32_t)(it % NST) * GLU_STGH * 2;
            int k0 = it * BK;
            CP16(adst[0] + so, aptr[0] + k0);
            CP16(adst[1] + so, aptr[1] + k0);
            size_t wko = (size_t)k0 * ldB;
            CP16(bdst + so,            b1p + wko);
            CP16(bdst + so + 2304 * 2, b3p + wko);
        }
        CP_COMMIT();
    };

    const int lane = tid & 31, wid = tid >> 5;
    const int g = lane >> 2, t = lane & 3;
    const int wm = wid >> 1, wn = wid & 1;
    const int hi = lane >> 4;          // 0: k-lo half, 1: k-hi half

    // precompute per-lane ldmatrix byte offsets (within stage)
    uint32_t aoffb[2][2];              // [mf][s]
    #pragma unroll
    for (int mf = 0; mf < 2; mf++) {
        int row = wm * 32 + mf * 16 + (lane & 15);
        #pragma unroll
        for (int s = 0; s < 2; s++) {
            int chunk = (s * 2 + hi) ^ ((row >> 1) & 3);
            aoffb[mf][s] = (uint32_t)(row * 32 + chunk * 8) * 2;
        }
    }
    uint32_t boffb[2][2];              // [nt][s] (B1; B3 = +2304*2)
    #pragma unroll
    for (int nt = 0; nt < 2; nt++) {
        int n_off = wn * 32 + nt * 16 + hi * 8;
        #pragma unroll
        for (int s = 0; s < 2; s++) {
            int kl = s * 16 + ((lane >> 3) & 1) * 8 + (lane & 7);
            boffb[nt][s] = (uint32_t)(4096 + kl * 72 + n_off) * 2;
        }
    }

    float acc1[2][4][4] = {}, acc3[2][4][4] = {};

    for (int p = 0; p < NST - 1; p++) load_stage(p);

    for (int it = 0; it < nit; it++) {
        CP_WAIT2();
        __syncthreads();
        load_stage(it + NST - 1);
        uint32_t stb = sb + (uint32_t)(it % NST) * GLU_STGH * 2;
        #pragma unroll
        for (int s = 0; s < 2; s++) {
            uint32_t a[2][4], b1r[2][4], b3r[2][4];
            #pragma unroll
            for (int mf = 0; mf < 2; mf++)
                LDSM4(a[mf][0], a[mf][1], a[mf][2], a[mf][3], stb + aoffb[mf][s]);
            #pragma unroll
            for (int nt = 0; nt < 2; nt++) {
                LDSM4T(b1r[nt][0], b1r[nt][1], b1r[nt][2], b1r[nt][3], stb + boffb[nt][s]);
                LDSM4T(b3r[nt][0], b3r[nt][1], b3r[nt][2], b3r[nt][3], stb + boffb[nt][s] + 2304 * 2);
            }
            #pragma unroll
            for (int mf = 0; mf < 2; mf++)
                #pragma unroll
                for (int nf = 0; nf < 4; nf++) {
                    mmah(acc1[mf][nf], a[mf], b1r[nf >> 1][(nf & 1) * 2], b1r[nf >> 1][(nf & 1) * 2 + 1]);
                    mmah(acc3[mf][nf], a[mf], b3r[nf >> 1][(nf & 1) * 2], b3r[nf >> 1][(nf & 1) * 2 + 1]);
                }
        }
    }

    // epilogue: C = fp16(silu(acc1) * acc3)
    #pragma unroll
    for (int mf = 0; mf < 2; mf++) {
        #pragma unroll
        for (int nf = 0; nf < 4; nf++) {
            int r0  = m0 + wm * 32 + mf * 16 + g;
            int col = n0 + wn * 32 + nf * 8 + t * 2;
            if (r0 < M) {
                uint32_t v = pack_h2(silu_f(acc1[mf][nf][0]) * acc3[mf][nf][0],
                                     silu_f(acc1[mf][nf][1]) * acc3[mf][nf][1]);
                *(uint32_t*)&C[(size_t)r0 * ldC + col] = v;
            }
            int r1 = r0 + 8;
            if (r1 < M) {
                uint32_t v = pack_h2(silu_f(acc1[mf][nf][2]) * acc3[mf][nf][2],
                                     silu_f(acc1[mf][nf][3]) * acc3[mf][nf][3]);
                *(uint32_t*)&C[(size_t)r1 * ldC + col] = v;
            }
        }
    }
}

// ---------------- merged down-proj GEMM (fp16 mma + ldmatrix) ----------------
// BM=128, BN=128, BK=32, 256 threads, 8 warps = 2(m) x 4(n), warp tile 64x32.
// z==0: shared (A=g_hsh, B=g_ws2h, w=1, token=m); z>=1: routed expert e=z-1
__global__ __launch_bounds__(256, 2)
void down_tc(float* __restrict__ out) {
    extern __shared__ __half smh[];
    const int tid = threadIdx.x;
    const int z = blockIdx.z, e = z - 1;

    int M, Kd;
    const __half *A, *B;
    if (z == 0) { M = TT; Kd = HSS; A = g_hsh; B = g_ws2h; }
    else {
        M = g_cnt[e]; Kd = HH;
        A = g_hidh + (size_t)e * TT * HH;
        B = g_w2h + (size_t)e * HH * DD;
    }
    const int m0 = blockIdx.y * 128, n0 = blockIdx.x * 128;
    if (m0 >= M) return;

    const uint32_t sb = smem_u32(smh);

    const __half* aptr[2];
    uint32_t adst[2];
    #pragma unroll
    for (int i = 0; i < 2; i++) {
        int id = tid + i * 256;
        int am = id >> 2, ac = id & 3;
        int r = m0 + am;
        if (r >= M) r = m0;
        aptr[i] = A + (size_t)r * Kd + ac * 8;
        adst[i] = sb + (uint32_t)(am * 32 + ((ac ^ ((am >> 1) & 3)) * 8)) * 2;
    }
    const __half* bptr[2];
    uint32_t bdst[2];
    #pragma unroll
    for (int i = 0; i < 2; i++) {
        int id = tid + i * 256;
        int k = id >> 4, nch = id & 15;                // row 0..31, chunk 0..15
        bptr[i] = B + (size_t)k * DD + n0 + nch * 8;
        bdst[i] = sb + (uint32_t)(4096 + k * 136 + nch * 8) * 2;
    }
    const int nit = Kd / BK;  // 32 or 16

    auto load_stage = [&](int it) {
        if (it < nit) {
            uint32_t so = (uint32_t)(it % NST) * DN_STGH * 2;
            int k0 = it * BK;
            CP16(adst[0] + so, aptr[0] + k0);
            CP16(adst[1] + so, aptr[1] + k0);
            size_t wko = (size_t)k0 * DD;
            CP16(bdst[0] + so, bptr[0] + wko);
            CP16(bdst[1] + so, bptr[1] + wko);
        }
        CP_COMMIT();
    };

    const int lane = tid & 31, wid = tid >> 5;
    const int g = lane >> 2, t = lane & 3;
    const int wm = wid >> 2, wn = wid & 3;
    const int hi = lane >> 4;

    uint32_t aoffb[4][2];              // [mf][s]
    #pragma unroll
    for (int mf = 0; mf < 4; mf++) {
        int row = wm * 64 + mf * 16 + (lane & 15);
        #pragma unroll
        for (int s = 0; s < 2; s++) {
            int chunk = (s * 2 + hi) ^ ((row >> 1) & 3);
            aoffb[mf][s] = (uint32_t)(row * 32 + chunk * 8) * 2;
        }
    }
    uint32_t boffb[2][2];              // [nt][s]
    #pragma unroll
    for (int nt = 0; nt < 2; nt++) {
        int n_off = wn * 32 + nt * 16 + hi * 8;
        #pragma unroll
        for (int s = 0; s < 2; s++) {
            int kl = s * 16 + ((lane >> 3) & 1) * 8 + (lane & 7);
            boffb[nt][s] = (uint32_t)(4096 + kl * 136 + n_off) * 2;
        }
    }

    float acc[4][4][4] = {};

    for (int p = 0; p < NST - 1; p++) load_stage(p);

    for (int it = 0; it < nit; it++) {
        CP_WAIT2();
        __syncthreads();
        load_stage(it + NST - 1);
        uint32_t stb = sb + (uint32_t)(it % NST) * DN_STGH * 2;
        #pragma unroll
        for (int s = 0; s < 2; s++) {
            uint32_t a[4][4], br[2][4];
            #pragma unroll
            for (int mf = 0; mf < 4; mf++)
                LDSM4(a[mf][0], a[mf][1], a[mf][2], a[mf][3], stb + aoffb[mf][s]);
            #pragma unroll
            for (int nt = 0; nt < 2; nt++)
                LDSM4T(br[nt][0], br[nt][1], br[nt][2], br[nt][3], stb + boffb[nt][s]);
            #pragma unroll
            for (int mf = 0; mf < 4; mf++)
                #pragma unroll
                for (int nf = 0; nf < 4; nf++)
                    mmah(acc[mf][nf], a[mf], br[nf >> 1][(nf & 1) * 2], br[nf >> 1][(nf & 1) * 2 + 1]);
        }
    }

    #pragma unroll
    for (int mf = 0; mf < 4; mf++) {
        #pragma unroll
        for (int nf = 0; nf < 4; nf++) {
            int r0  = m0 + wm * 64 + mf * 16 + g;
            int col = n0 + wn * 32 + nf * 8 + t * 2;
            if (r0 < M) {
                int tk; float w;
                if (z == 0) { tk = r0; w = 1.f; }
                else        { tk = g_tok[e * TT + r0]; w = g_wt[e * TT + r0]; }
                float* orow = out + (size_t)tk * DD + col;
                atomicAdd(orow,     w * acc[mf][nf][0]);
                atomicAdd(orow + 1, w * acc[mf][nf][1]);
            }
            int r1 = r0 + 8;
            if (r1 < M) {
                int tk; float w;
                if (z == 0) { tk = r1; w = 1.f; }
                else        { tk = g_tok[e * TT + r1]; w = g_wt[e * TT + r1]; }
                float* orow = out + (size_t)tk * DD + col;
                atomicAdd(orow,     w * acc[mf][nf][2]);
                atomicAdd(orow + 1, w * acc[mf][nf][3]);
            }
        }
    }
}

// ---------------- launch -----------------------------------------------------
extern "C" void kernel_launch(void* const* d_in, const int* in_sizes, int n_in,
                              void* d_out, int out_size) {
    (void)in_sizes; (void)n_in; (void)out_size;
    const float* x   = (const float*)d_in[0];
    const float* gw  = (const float*)d_in[1];
    const float* w1  = (const float*)d_in[2];
    const float* w3  = (const float*)d_in[3];
    const float* w2  = (const float*)d_in[4];
    const float* ws1 = (const float*)d_in[5];
    const float* ws3 = (const float*)d_in[6];
    const float* ws2 = (const float*)d_in[7];
    float* out = (float*)d_out;

    cudaFuncSetAttribute(glu_tc,  cudaFuncAttributeMaxDynamicSharedMemorySize, GLU_SMEMB);
    cudaFuncSetAttribute(down_tc, cudaFuncAttributeMaxDynamicSharedMemorySize, DN_SMEMB);

    __half *w1h, *w3h, *w2h;
    cudaGetSymbolAddress((void**)&w1h, g_w1h);
    cudaGetSymbolAddress((void**)&w3h, g_w3h);
    cudaGetSymbolAddress((void**)&w2h, g_w2h);

    init_kernel<<<1, 32>>>();
    router_kernel<<<TT / 8, 256>>>(x, gw);

    PrepArgs pa;
    pa.big[0] = w1; pa.bigd[0] = w1h;
    pa.big[1] = w3; pa.bigd[1] = w3h;
    pa.big[2] = w2; pa.bigd[2] = w2h;
    pa.ws1 = ws1; pa.ws3 = ws3; pa.ws2 = ws2;
    pa.out = out;
    prep_kernel<<<dim3(296, 4), 256>>>(pa);

    // fused SwiGLU: shared expert (z=0) + routed experts (z=1..8)
    glu_tc<<<dim3(16, 16, 1 + EE), 256, GLU_SMEMB>>>();

    // merged down-proj: all contributions atomically accumulated
    down_tc<<<dim3(8, 16, 1 + EE), 256, DN_SMEMB>>>(out);
}

// round 16
// speedup vs baseline: 1.3381x; 1.2862x over previous
#include <cuda_runtime.h>
#include <cuda_fp16.h>
#include <math.h>
#include <stdint.h>

#define TT  2048
#define DD  1024
#define HH  512
#define HSS 1024
#define EE  8
#define BK  32
#define NST 4

// stage sizes in halves
#define GLU_STGH 8704                  // A 128x32 = 4096, B1 32x72 = 2304, B3 2304
#define GLU_SMEMB (NST * GLU_STGH * 2) // 69632 B
#define DN_STGH  8448                  // A 4096, B 32x136 = 4352
#define DN_SMEMB  (NST * DN_STGH * 2)  // 67584 B

// ---------------- scratch ----------------------------------------------------
__device__ __half g_xh  [(size_t)TT * DD];        // fp16 input
__device__ __half g_hsh [(size_t)TT * HSS];       // fp16 shared hidden
__device__ __half g_hidh[(size_t)EE * TT * HH];   // fp16 routed hidden
__device__ __half g_w1h [(size_t)EE * DD * HH];
__device__ __half g_w3h [(size_t)EE * DD * HH];
__device__ __half g_w2h [(size_t)EE * HH * DD];
__device__ __half g_ws1h[(size_t)DD * HSS];
__device__ __half g_ws3h[(size_t)DD * HSS];
__device__ __half g_ws2h[(size_t)HSS * DD];
__device__ int    g_cnt[EE];
__device__ int    g_tok[EE * TT];
__device__ float  g_wt [EE * TT];

// ---------------- helpers ----------------------------------------------------
__device__ __forceinline__ uint32_t smem_u32(const void* p) {
    uint32_t a;
    asm("{ .reg .u64 t; cvta.to.shared.u64 t, %1; cvt.u32.u64 %0, t; }" : "=r"(a) : "l"(p));
    return a;
}
#define CP16(dst, src) \
    asm volatile("cp.async.cg.shared.global [%0], [%1], 16;" :: "r"((uint32_t)(dst)), "l"(src))
#define CP_COMMIT() asm volatile("cp.async.commit_group;" ::: "memory")
#define CP_WAIT2()  asm volatile("cp.async.wait_group 2;" ::: "memory")

#define LDSM4(r0, r1, r2, r3, addr) \
    asm volatile("ldmatrix.sync.aligned.m8n8.x4.shared.b16 {%0,%1,%2,%3}, [%4];" \
        : "=r"(r0), "=r"(r1), "=r"(r2), "=r"(r3) : "r"(addr))
#define LDSM4T(r0, r1, r2, r3, addr) \
    asm volatile("ldmatrix.sync.aligned.m8n8.x4.trans.shared.b16 {%0,%1,%2,%3}, [%4];" \
        : "=r"(r0), "=r"(r1), "=r"(r2), "=r"(r3) : "r"(addr))

__device__ __forceinline__ void mmah(float* c, const uint32_t* a, uint32_t b0, uint32_t b1) {
    asm volatile(
        "mma.sync.aligned.m16n8k16.row.col.f32.f16.f16.f32 "
        "{%0,%1,%2,%3}, {%4,%5,%6,%7}, {%8,%9}, {%0,%1,%2,%3};"
        : "+f"(c[0]), "+f"(c[1]), "+f"(c[2]), "+f"(c[3])
        : "r"(a[0]), "r"(a[1]), "r"(a[2]), "r"(a[3]), "r"(b0), "r"(b1));
}
__device__ __forceinline__ float silu_f(float v) { return v / (1.f + expf(-v)); }

__device__ __forceinline__ uint32_t pack_h2(float a, float b) {
    __half2 h = __floats2half2_rn(a, b);
    return ((uint32_t)__half_as_ushort(__high2half(h)) << 16)
         | (uint32_t)__half_as_ushort(__low2half(h));
}

// vector reduction: one 8B red instead of two scalar atomicAdds
#define RED2(ptr, a, b) \
    asm volatile("red.global.add.v2.f32 [%0], {%1, %2};" :: "l"(ptr), "f"(a), "f"(b) : "memory")

// ---------------- init / zero / cvt ------------------------------------------
__global__ void init_kernel() { if (threadIdx.x < EE) g_cnt[threadIdx.x] = 0; }

__global__ void zero_out_kernel(float* __restrict__ out) {
    int i = blockIdx.x * blockDim.x + threadIdx.x;
    ((float4*)out)[i] = make_float4(0.f, 0.f, 0.f, 0.f);
}

// merged fp32 -> fp16 conversion: gridDim.y selects the array; 8 floats/thread/iter
struct CvtArgs {
    const float* src[6];
    __half* dst[6];
    int n8[6];
};
__global__ void cvt_all_kernel(CvtArgs args) {
    const int y = blockIdx.y;
    const float4* s = (const float4*)args.src[y];
    uint4* d = (uint4*)args.dst[y];
    const int n8 = args.n8[y];
    int i = blockIdx.x * blockDim.x + threadIdx.x;
    const int stride = gridDim.x * blockDim.x;
    for (; i < n8; i += stride) {
        float4 v0 = s[i * 2];
        float4 v1 = s[i * 2 + 1];
        uint4 o;
        o.x = pack_h2(v0.x, v0.y);
        o.y = pack_h2(v0.z, v0.w);
        o.z = pack_h2(v1.x, v1.y);
        o.w = pack_h2(v1.z, v1.w);
        d[i] = o;
    }
}

// ---------------- router: scores + top-2 + fp16 x copy -----------------------
__global__ void router_kernel(const float* __restrict__ x, const float* __restrict__ gw) {
    int warp = (blockIdx.x * blockDim.x + threadIdx.x) >> 5;
    int lane = threadIdx.x & 31;
    if (warp >= TT) return;
    const float* xr = x + (size_t)warp * DD;
    __half* xo = g_xh + (size_t)warp * DD;
    float acc[EE];
    #pragma unroll
    for (int e = 0; e < EE; e++) acc[e] = 0.f;
    for (int d = lane; d < DD; d += 32) {
        float xv = xr[d];
        xo[d] = __float2half_rn(xv);
        const float* g = gw + (size_t)d * EE;
        #pragma unroll
        for (int e = 0; e < EE; e++) acc[e] += xv * g[e];
    }
    #pragma unroll
    for (int e = 0; e < EE; e++) {
        #pragma unroll
        for (int o = 16; o > 0; o >>= 1) acc[e] += __shfl_xor_sync(0xFFFFFFFFu, acc[e], o);
    }
    if (lane == 0) {
        float s[EE];
        #pragma unroll
        for (int e = 0; e < EE; e++) s[e] = 1.f / (1.f + expf(-acc[e]));
        int i0 = 0;
        #pragma unroll
        for (int e = 1; e < EE; e++) if (s[e] > s[i0]) i0 = e;
        int i1 = (i0 == 0) ? 1 : 0;
        #pragma unroll
        for (int e = 0; e < EE; e++) { if (e != i0 && s[e] > s[i1]) i1 = e; }
        float sum = s[i0] + s[i1];
        int p0 = atomicAdd(&g_cnt[i0], 1);
        g_tok[i0 * TT + p0] = warp; g_wt[i0 * TT + p0] = s[i0] / sum;
        int p1 = atomicAdd(&g_cnt[i1], 1);
        g_tok[i1 * TT + p1] = warp; g_wt[i1 * TT + p1] = s[i1] / sum;
    }
}

// ---------------- fused SwiGLU GEMM (fp16 mma + ldmatrix) --------------------
// BM=128, BN=64, BK=32, 256 threads, 8 warps = 4(m) x 2(n), warp tile 32x32.
// z==0: shared (A=g_xh, B=g_ws1h/g_ws3h ld HSS, C=g_hsh); z>=1: expert e=z-1
__global__ __launch_bounds__(256, 2)
void glu_tc() {
    extern __shared__ __half smh[];
    const int tid = threadIdx.x;
    const int z = blockIdx.z, e = z - 1;

    int M, ldB, ldC;
    const __half *B1, *B3;
    const int* tok = nullptr;
    __half* C;
    if (z == 0) {
        M = TT; ldB = HSS; ldC = HSS;
        B1 = g_ws1h; B3 = g_ws3h; C = g_hsh;
    } else {
        if (blockIdx.x >= HH / 64) return;
        M = g_cnt[e]; ldB = HH; ldC = HH;
        tok = g_tok + e * TT;
        B1 = g_w1h + (size_t)e * DD * HH;
        B3 = g_w3h + (size_t)e * DD * HH;
        C  = g_hidh + (size_t)e * TT * HH;
    }
    const int m0 = blockIdx.y * 128, n0 = blockIdx.x * 64;
    if (m0 >= M) return;

    const uint32_t sb = smem_u32(smh);

    // producers: A 2 chunks (16B = 8 halves), B1/B3 1 chunk each, per stage
    const __half* aptr[2];
    uint32_t adst[2];
    #pragma unroll
    for (int i = 0; i < 2; i++) {
        int id = tid + i * 256;
        int am = id >> 2, ac = id & 3;                 // row 0..127, chunk 0..3
        int gm = m0 + am;
        int sr = (z == 0) ? gm : ((gm < M) ? tok[gm] : tok[m0]);
        aptr[i] = g_xh + (size_t)sr * DD + ac * 8;
        adst[i] = sb + (uint32_t)(am * 32 + ((ac ^ ((am >> 1) & 3)) * 8)) * 2;
    }
    const int bk = tid >> 3, bch = tid & 7;            // row 0..31, chunk 0..7
    const __half* b1p = B1 + (size_t)bk * ldB + n0 + bch * 8;
    const __half* b3p = B3 + (size_t)bk * ldB + n0 + bch * 8;
    const uint32_t bdst = sb + (uint32_t)(4096 + bk * 72 + bch * 8) * 2;

    const int nit = DD / BK;  // 32

    auto load_stage = [&](int it) {
        if (it < nit) {
            uint32_t so = (uint32_t)(it % NST) * GLU_STGH * 2;
            int k0 = it * BK;
            CP16(adst[0] + so, aptr[0] + k0);
            CP16(adst[1] + so, aptr[1] + k0);
            size_t wko = (size_t)k0 * ldB;
            CP16(bdst + so,            b1p + wko);
            CP16(bdst + so + 2304 * 2, b3p + wko);
        }
        CP_COMMIT();
    };

    const int lane = tid & 31, wid = tid >> 5;
    const int g = lane >> 2, t = lane & 3;
    const int wm = wid >> 1, wn = wid & 1;
    const int hi = lane >> 4;          // 0: k-lo half, 1: k-hi half

    // precompute per-lane ldmatrix byte offsets (within stage)
    uint32_t aoffb[2][2];              // [mf][s]
    #pragma unroll
    for (int mf = 0; mf < 2; mf++) {
        int row = wm * 32 + mf * 16 + (lane & 15);
        #pragma unroll
        for (int s = 0; s < 2; s++) {
            int chunk = (s * 2 + hi) ^ ((row >> 1) & 3);
            aoffb[mf][s] = (uint32_t)(row * 32 + chunk * 8) * 2;
        }
    }
    uint32_t boffb[2][2];              // [nt][s] (B1; B3 = +2304*2)
    #pragma unroll
    for (int nt = 0; nt < 2; nt++) {
        int n_off = wn * 32 + nt * 16 + hi * 8;
        #pragma unroll
        for (int s = 0; s < 2; s++) {
            int kl = s * 16 + ((lane >> 3) & 1) * 8 + (lane & 7);
            boffb[nt][s] = (uint32_t)(4096 + kl * 72 + n_off) * 2;
        }
    }

    float acc1[2][4][4] = {}, acc3[2][4][4] = {};

    for (int p = 0; p < NST - 1; p++) load_stage(p);

    for (int it = 0; it < nit; it++) {
        CP_WAIT2();
        __syncthreads();
        load_stage(it + NST - 1);
        uint32_t stb = sb + (uint32_t)(it % NST) * GLU_STGH * 2;
        #pragma unroll
        for (int s = 0; s < 2; s++) {
            uint32_t a[2][4], b1r[2][4], b3r[2][4];
            #pragma unroll
            for (int mf = 0; mf < 2; mf++)
                LDSM4(a[mf][0], a[mf][1], a[mf][2], a[mf][3], stb + aoffb[mf][s]);
            #pragma unroll
            for (int nt = 0; nt < 2; nt++) {
                LDSM4T(b1r[nt][0], b1r[nt][1], b1r[nt][2], b1r[nt][3], stb + boffb[nt][s]);
                LDSM4T(b3r[nt][0], b3r[nt][1], b3r[nt][2], b3r[nt][3], stb + boffb[nt][s] + 2304 * 2);
            }
            #pragma unroll
            for (int mf = 0; mf < 2; mf++)
                #pragma unroll
                for (int nf = 0; nf < 4; nf++) {
                    mmah(acc1[mf][nf], a[mf], b1r[nf >> 1][(nf & 1) * 2], b1r[nf >> 1][(nf & 1) * 2 + 1]);
                    mmah(acc3[mf][nf], a[mf], b3r[nf >> 1][(nf & 1) * 2], b3r[nf >> 1][(nf & 1) * 2 + 1]);
                }
        }
    }

    // epilogue: C = fp16(silu(acc1) * acc3)
    #pragma unroll
    for (int mf = 0; mf < 2; mf++) {
        #pragma unroll
        for (int nf = 0; nf < 4; nf++) {
            int r0  = m0 + wm * 32 + mf * 16 + g;
            int col = n0 + wn * 32 + nf * 8 + t * 2;
            if (r0 < M) {
                uint32_t v = pack_h2(silu_f(acc1[mf][nf][0]) * acc3[mf][nf][0],
                                     silu_f(acc1[mf][nf][1]) * acc3[mf][nf][1]);
                *(uint32_t*)&C[(size_t)r0 * ldC + col] = v;
            }
            int r1 = r0 + 8;
            if (r1 < M) {
                uint32_t v = pack_h2(silu_f(acc1[mf][nf][2]) * acc3[mf][nf][2],
                                     silu_f(acc1[mf][nf][3]) * acc3[mf][nf][3]);
                *(uint32_t*)&C[(size_t)r1 * ldC + col] = v;
            }
        }
    }
}

// ---------------- merged down-proj GEMM (fp16 mma + ldmatrix) ----------------
// BM=128, BN=128, BK=32, 256 threads, 8 warps = 2(m) x 4(n), warp tile 64x32.
// z==0: shared (A=g_hsh, B=g_ws2h, w=1, token=m); z>=1: routed expert e=z-1
__global__ __launch_bounds__(256, 2)
void down_tc(float* __restrict__ out) {
    extern __shared__ __half smh[];
    const int tid = threadIdx.x;
    const int z = blockIdx.z, e = z - 1;

    int M, Kd;
    const __half *A, *B;
    if (z == 0) { M = TT; Kd = HSS; A = g_hsh; B = g_ws2h; }
    else {
        M = g_cnt[e]; Kd = HH;
        A = g_hidh + (size_t)e * TT * HH;
        B = g_w2h + (size_t)e * HH * DD;
    }
    const int m0 = blockIdx.y * 128, n0 = blockIdx.x * 128;
    if (m0 >= M) return;

    const uint32_t sb = smem_u32(smh);

    const __half* aptr[2];
    uint32_t adst[2];
    #pragma unroll
    for (int i = 0; i < 2; i++) {
        int id = tid + i * 256;
        int am = id >> 2, ac = id & 3;
        int r = m0 + am;
        if (r >= M) r = m0;
        aptr[i] = A + (size_t)r * Kd + ac * 8;
        adst[i] = sb + (uint32_t)(am * 32 + ((ac ^ ((am >> 1) & 3)) * 8)) * 2;
    }
    const __half* bptr[2];
    uint32_t bdst[2];
    #pragma unroll
    for (int i = 0; i < 2; i++) {
        int id = tid + i * 256;
        int k = id >> 4, nch = id & 15;                // row 0..31, chunk 0..15
        bptr[i] = B + (size_t)k * DD + n0 + nch * 8;
        bdst[i] = sb + (uint32_t)(4096 + k * 136 + nch * 8) * 2;
    }
    const int nit = Kd / BK;  // 32 or 16

    auto load_stage = [&](int it) {
        if (it < nit) {
            uint32_t so = (uint32_t)(it % NST) * DN_STGH * 2;
            int k0 = it * BK;
            CP16(adst[0] + so, aptr[0] + k0);
            CP16(adst[1] + so, aptr[1] + k0);
            size_t wko = (size_t)k0 * DD;
            CP16(bdst[0] + so, bptr[0] + wko);
            CP16(bdst[1] + so, bptr[1] + wko);
        }
        CP_COMMIT();
    };

    const int lane = tid & 31, wid = tid >> 5;
    const int g = lane >> 2, t = lane & 3;
    const int wm = wid >> 2, wn = wid & 3;
    const int hi = lane >> 4;

    uint32_t aoffb[4][2];              // [mf][s]
    #pragma unroll
    for (int mf = 0; mf < 4; mf++) {
        int row = wm * 64 + mf * 16 + (lane & 15);
        #pragma unroll
        for (int s = 0; s < 2; s++) {
            int chunk = (s * 2 + hi) ^ ((row >> 1) & 3);
            aoffb[mf][s] = (uint32_t)(row * 32 + chunk * 8) * 2;
        }
    }
    uint32_t boffb[2][2];              // [nt][s]
    #pragma unroll
    for (int nt = 0; nt < 2; nt++) {
        int n_off = wn * 32 + nt * 16 + hi * 8;
        #pragma unroll
        for (int s = 0; s < 2; s++) {
            int kl = s * 16 + ((lane >> 3) & 1) * 8 + (lane & 7);
            boffb[nt][s] = (uint32_t)(4096 + kl * 136 + n_off) * 2;
        }
    }

    float acc[4][4][4] = {};

    for (int p = 0; p < NST - 1; p++) load_stage(p);

    for (int it = 0; it < nit; it++) {
        CP_WAIT2();
        __syncthreads();
        load_stage(it + NST - 1);
        uint32_t stb = sb + (uint32_t)(it % NST) * DN_STGH * 2;
        #pragma unroll
        for (int s = 0; s < 2; s++) {
            uint32_t a[4][4], br[2][4];
            #pragma unroll
            for (int mf = 0; mf < 4; mf++)
                LDSM4(a[mf][0], a[mf][1], a[mf][2], a[mf][3], stb + aoffb[mf][s]);
            #pragma unroll
            for (int nt = 0; nt < 2; nt++)
                LDSM4T(br[nt][0], br[nt][1], br[nt][2], br[nt][3], stb + boffb[nt][s]);
            #pragma unroll
            for (int mf = 0; mf < 4; mf++)
                #pragma unroll
                for (int nf = 0; nf < 4; nf++)
                    mmah(acc[mf][nf], a[mf], br[nf >> 1][(nf & 1) * 2], br[nf >> 1][(nf & 1) * 2 + 1]);
        }
    }

    #pragma unroll
    for (int mf = 0; mf < 4; mf++) {
        #pragma unroll
        for (int nf = 0; nf < 4; nf++) {
            int r0  = m0 + wm * 64 + mf * 16 + g;
            int col = n0 + wn * 32 + nf * 8 + t * 2;
            if (r0 < M) {
                int tk; float w;
                if (z == 0) { tk = r0; w = 1.f; }
                else        { tk = g_tok[e * TT + r0]; w = g_wt[e * TT + r0]; }
                float* orow = out + (size_t)tk * DD + col;
                RED2(orow, w * acc[mf][nf][0], w * acc[mf][nf][1]);
            }
            int r1 = r0 + 8;
            if (r1 < M) {
                int tk; float w;
                if (z == 0) { tk = r1; w = 1.f; }
                else        { tk = g_tok[e * TT + r1]; w = g_wt[e * TT + r1]; }
                float* orow = out + (size_t)tk * DD + col;
                RED2(orow, w * acc[mf][nf][2], w * acc[mf][nf][3]);
            }
        }
    }
}

// ---------------- launch -----------------------------------------------------
extern "C" void kernel_launch(void* const* d_in, const int* in_sizes, int n_in,
                              void* d_out, int out_size) {
    (void)in_sizes; (void)n_in; (void)out_size;
    const float* x   = (const float*)d_in[0];
    const float* gw  = (const float*)d_in[1];
    const float* w1  = (const float*)d_in[2];
    const float* w3  = (const float*)d_in[3];
    const float* w2  = (const float*)d_in[4];
    const float* ws1 = (const float*)d_in[5];
    const float* ws3 = (const float*)d_in[6];
    const float* ws2 = (const float*)d_in[7];
    float* out = (float*)d_out;

    cudaFuncSetAttribute(glu_tc,  cudaFuncAttributeMaxDynamicSharedMemorySize, GLU_SMEMB);
    cudaFuncSetAttribute(down_tc, cudaFuncAttributeMaxDynamicSharedMemorySize, DN_SMEMB);

    __half *w1h, *w3h, *w2h, *ws1h, *ws3h, *ws2h;
    cudaGetSymbolAddress((void**)&w1h,  g_w1h);
    cudaGetSymbolAddress((void**)&w3h,  g_w3h);
    cudaGetSymbolAddress((void**)&w2h,  g_w2h);
    cudaGetSymbolAddress((void**)&ws1h, g_ws1h);
    cudaGetSymbolAddress((void**)&ws3h, g_ws3h);
    cudaGetSymbolAddress((void**)&ws2h, g_ws2h);

    init_kernel<<<1, 32>>>();
    zero_out_kernel<<<(TT * DD / 4) / 256, 256>>>(out);
    router_kernel<<<TT / 8, 256>>>(x, gw);

    CvtArgs ca;
    ca.src[0] = w1;  ca.dst[0] = w1h;  ca.n8[0] = EE * DD * HH / 8;
    ca.src[1] = w3;  ca.dst[1] = w3h;  ca.n8[1] = EE * DD * HH / 8;
    ca.src[2] = w2;  ca.dst[2] = w2h;  ca.n8[2] = EE * HH * DD / 8;
    ca.src[3] = ws1; ca.dst[3] = ws1h; ca.n8[3] = DD * HSS / 8;
    ca.src[4] = ws3; ca.dst[4] = ws3h; ca.n8[4] = DD * HSS / 8;
    ca.src[5] = ws2; ca.dst[5] = ws2h; ca.n8[5] = HSS * DD / 8;
    cvt_all_kernel<<<dim3(296, 6), 256>>>(ca);

    // fused SwiGLU: shared expert (z=0) + routed experts (z=1..8)
    glu_tc<<<dim3(16, 16, 1 + EE), 256, GLU_SMEMB>>>();

    // merged down-proj: all contributions atomically accumulated (vector red)
    down_tc<<<dim3(8, 16, 1 + EE), 256, DN_SMEMB>>>(out);
}